// round 1
// baseline (speedup 1.0000x reference)
#include <cuda_runtime.h>
#include <math.h>

#define BG   128
#define NPG  256
#define EPG  2048
#define EMB  256
#define NL   5
#define NTOT (BG*NPG)     // 32768 nodes
#define ETOT (BG*EPG)     // 262144 edges

typedef unsigned long long ull;

// ------------------------------ scratch (device globals; no allocs) ---------
__device__ ull   g_pack[(size_t)BG*NPG*NPG];   // packed last-write-wins adjacency
__device__ float g_A   [(size_t)BG*NPG*NPG];   // normalized adjacency
__device__ float g_h  [NTOT*EMB];
__device__ float g_x1 [NTOT*EMB];
__device__ float g_x2 [NTOT*EMB];
__device__ float g_hin[NTOT*EMB];
__device__ float g_z  [NTOT*EMB];
__device__ float g_t  [NTOT*2*EMB];
__device__ float g_h2 [NTOT*EMB];
__device__ float g_vn [BG*EMB];
__device__ float g_vt [BG*EMB];
__device__ float g_vh [BG*2*EMB];
__device__ float g_ewt[16];
__device__ int   g_deg[NTOT];
__device__ int   g_ptr[NTOT];
__device__ int   g_cur[NTOT];
__device__ int   g_csrc[ETOT];
__device__ int   g_cea [ETOT];
__device__ float g_sum[2*EMB];
__device__ float g_sq [2*EMB];
__device__ float g_scale[2*EMB];
__device__ float g_shift[2*EMB];

// ------------------------------ setup kernels -------------------------------
__global__ void k_zero() {
    size_t i = (size_t)blockIdx.x * 256 + threadIdx.x;
    if (i < (size_t)BG*NPG*NPG) g_pack[i] = 0ull;
    if (i < NTOT) g_deg[i] = 0;
}

// 16 per-bond-type edge weights: sigmoid(<bond_emb_h[t], w> + b)
__global__ void k_ewt(const float* __restrict__ bh, const float* __restrict__ w,
                      const float* __restrict__ b) {
    int warp = threadIdx.x >> 5, lane = threadIdx.x & 31;
    if (warp < 16) {
        float v = bh[warp*64 + lane] * w[lane] + bh[warp*64 + 32 + lane] * w[32 + lane];
        #pragma unroll
        for (int o = 16; o; o >>= 1) v += __shfl_down_sync(0xffffffffu, v, o);
        if (lane == 0) g_ewt[warp] = 1.f / (1.f + expf(-(v + b[0])));
    }
}

// scatter edges into packed adjacency (last edge index wins, matching XLA
// sequential scatter-set) + degree count for CSR
__global__ void k_scatter(const int* __restrict__ lei, const int* __restrict__ eai) {
    int idx = blockIdx.x * 256 + threadIdx.x;
    if (idx >= ETOT) return;
    int b = idx / EPG, k = idx - b * EPG;
    int s = lei[(size_t)b*2*EPG + k];
    int d = lei[(size_t)b*2*EPG + EPG + k];
    int t = eai[idx];
    float w = g_ewt[t];
    ull key = ((ull)(k + 1) << 32) | (ull)__float_as_uint(w);
    atomicMax(&g_pack[(size_t)b*NPG*NPG + (size_t)s*NPG + d], key);
    atomicAdd(&g_deg[b*NPG + d], 1);
}

// unpack + eye + row/col normalize:  A[i,j] = adj[i,j]*rsqrt(cs_i)*rsqrt(rs_j)
__global__ void k_adjfin() {
    int g = blockIdx.x, tid = threadIdx.x;
    __shared__ float cs[NPG], rs[NPG];
    const ull* P = g_pack + (size_t)g*NPG*NPG;
    float*     A = g_A    + (size_t)g*NPG*NPG;
    float c = 0.f;
    for (int i = 0; i < NPG; i++) {            // column tid
        ull p = P[(size_t)i*NPG + tid];
        float v = p ? __uint_as_float((unsigned)(p & 0xffffffffu)) : 0.f;
        if (i == tid) v += 1.f;
        A[(size_t)i*NPG + tid] = v;
        c += v;
    }
    cs[tid] = rsqrtf(c);
    __syncthreads();
    float r = 0.f;
    for (int j = 0; j < NPG; j++) r += A[(size_t)tid*NPG + j];   // row tid
    rs[tid] = rsqrtf(r);
    __syncthreads();
    for (int i = 0; i < NPG; i++)
        A[(size_t)i*NPG + tid] *= cs[i] * rs[tid];
}

// per-graph exclusive scan of degrees -> CSR start pointers
__global__ void k_scan() {
    int g = blockIdx.x, tid = threadIdx.x;
    __shared__ int s[NPG];
    int d = g_deg[g*NPG + tid];
    s[tid] = d;
    __syncthreads();
    for (int off = 1; off < NPG; off <<= 1) {
        int v = (tid >= off) ? s[tid - off] : 0;
        __syncthreads();
        s[tid] += v;
        __syncthreads();
    }
    int excl = s[tid] - d;
    g_ptr[g*NPG + tid] = g*EPG + excl;
    g_cur[g*NPG + tid] = g*EPG + excl;
}

__global__ void k_csrfill(const int* __restrict__ lei, const int* __restrict__ eai) {
    int idx = blockIdx.x * 256 + threadIdx.x;
    if (idx >= ETOT) return;
    int b = idx / EPG, k = idx - b * EPG;
    int s = lei[(size_t)b*2*EPG + k];
    int d = lei[(size_t)b*2*EPG + EPG + k];
    int pos = atomicAdd(&g_cur[b*NPG + d], 1);
    g_csrc[pos] = b*NPG + s;
    g_cea [pos] = eai[idx];
}

// h0 = atom_emb[atom_idx]; also seeds propagation x buffer
__global__ void k_gather(const int* __restrict__ aidx, const float* __restrict__ aemb) {
    int idx = blockIdx.x * 256 + threadIdx.x;     // NTOT*EMB threads
    int n = idx >> 8, c = idx & 255;
    float v = aemb[aidx[n]*EMB + c];
    g_h[idx]  = v;
    g_x1[idx] = v;
}

// ------------------------------ propagation GEMM ----------------------------
// per graph: Xout = A @ Xin ; g_h += Xout       (64x64 tiles, 4x4 per thread)
__global__ void __launch_bounds__(256)
k_propgemm(const float* __restrict__ Xin, float* __restrict__ Xout) {
    int g = blockIdx.z;
    const float* Ag = g_A + (size_t)g*NPG*NPG;
    const float* Bg = Xin + (size_t)g*NPG*EMB;
    float* Cg = Xout + (size_t)g*NPG*EMB;
    float* Yg = g_h  + (size_t)g*NPG*EMB;
    __shared__ float As[16][64], Bs[16][64];
    int tid = threadIdx.x;
    int tx = tid & 15, ty = tid >> 4;
    int bm = blockIdx.y << 6, bn = blockIdx.x << 6;
    int a_row = tid >> 2,  a_c = (tid & 3) << 2;
    int b_row = tid >> 4,  b_c = (tid & 15) << 2;
    float acc[4][4] = {};
    for (int k0 = 0; k0 < NPG; k0 += 16) {
        float4 av = *reinterpret_cast<const float4*>(Ag + (size_t)(bm + a_row)*NPG + k0 + a_c);
        As[a_c+0][a_row]=av.x; As[a_c+1][a_row]=av.y; As[a_c+2][a_row]=av.z; As[a_c+3][a_row]=av.w;
        *reinterpret_cast<float4*>(&Bs[b_row][b_c]) =
            *reinterpret_cast<const float4*>(Bg + (size_t)(k0 + b_row)*EMB + bn + b_c);
        __syncthreads();
        #pragma unroll
        for (int k = 0; k < 16; k++) {
            float4 a = *reinterpret_cast<const float4*>(&As[k][ty << 2]);
            float4 b = *reinterpret_cast<const float4*>(&Bs[k][tx << 2]);
            float aa[4] = {a.x,a.y,a.z,a.w}, bb[4] = {b.x,b.y,b.z,b.w};
            #pragma unroll
            for (int i = 0; i < 4; i++)
                #pragma unroll
                for (int j = 0; j < 4; j++) acc[i][j] = fmaf(aa[i], bb[j], acc[i][j]);
        }
        __syncthreads();
    }
    #pragma unroll
    for (int i = 0; i < 4; i++) {
        int r = bm + (ty << 2) + i;
        #pragma unroll
        for (int j = 0; j < 4; j++) {
            int c = bn + (tx << 2) + j;
            Cg[(size_t)r*EMB + c] = acc[i][j];
            Yg[(size_t)r*EMB + c] += acc[i][j];
        }
    }
}

__global__ void k_scale() {
    int idx = blockIdx.x * 256 + threadIdx.x;
    g_h[idx] *= 0.25f;    // /(order+1), order=3
}

// ------------------------------ GIN layer kernels ---------------------------
__global__ void k_initvn(const float* __restrict__ vemb) {
    int idx = blockIdx.x * 256 + threadIdx.x;     // BG*EMB
    g_vn[idx] = vemb[idx & 255];
}

__global__ void k_addvn() {
    int idx = blockIdx.x * 256 + threadIdx.x;     // NTOT*EMB
    int b = idx >> 16;                            // idx/(NPG*EMB)
    int c = idx & 255;
    float v = g_h[idx] + g_vn[b*EMB + c];
    g_h[idx] = v;
    g_hin[idx] = v;
}

// z[d] = (1+eps)*h[d] + sum_{edges into d} relu(h[src] + bond_emb_l[l][type])
__global__ void k_agg(const float* __restrict__ eembL, const float* __restrict__ epsp) {
    int n = blockIdx.x, c = threadIdx.x;
    int start = g_ptr[n], deg = g_deg[n];
    float val = 0.f;
    for (int k = 0; k < deg; k++) {
        int s = g_csrc[start + k];
        int t = g_cea [start + k];
        float m = g_h[(size_t)s*EMB + c] + eembL[t*EMB + c];
        val += fmaxf(m, 0.f);
    }
    float eps = *epsp;
    g_z[(size_t)n*EMB + c] = (1.f + eps) * g_h[(size_t)n*EMB + c] + val;
}

// generic GEMM: C[M,Nn] = A[M,K] @ B[K,Nn] + bias, optional relu
__global__ void __launch_bounds__(256)
k_gemm(const float* __restrict__ A, const float* __restrict__ Bm,
       const float* __restrict__ bias, float* __restrict__ C,
       int M, int Nn, int K, int act) {
    __shared__ float As[16][64], Bs[16][64];
    int tid = threadIdx.x;
    int tx = tid & 15, ty = tid >> 4;
    int bm = blockIdx.y << 6, bn = blockIdx.x << 6;
    int a_row = tid >> 2,  a_c = (tid & 3) << 2;
    int b_row = tid >> 4,  b_c = (tid & 15) << 2;
    const float* Ap = A  + (size_t)(bm + a_row)*K + a_c;
    const float* Bp = Bm + (size_t)b_row*Nn + bn + b_c;
    float acc[4][4] = {};
    for (int k0 = 0; k0 < K; k0 += 16) {
        float4 av = *reinterpret_cast<const float4*>(Ap + k0);
        As[a_c+0][a_row]=av.x; As[a_c+1][a_row]=av.y; As[a_c+2][a_row]=av.z; As[a_c+3][a_row]=av.w;
        *reinterpret_cast<float4*>(&Bs[b_row][b_c]) =
            *reinterpret_cast<const float4*>(Bp + (size_t)k0*Nn);
        __syncthreads();
        #pragma unroll
        for (int k = 0; k < 16; k++) {
            float4 a = *reinterpret_cast<const float4*>(&As[k][ty << 2]);
            float4 b = *reinterpret_cast<const float4*>(&Bs[k][tx << 2]);
            float aa[4] = {a.x,a.y,a.z,a.w}, bb[4] = {b.x,b.y,b.z,b.w};
            #pragma unroll
            for (int i = 0; i < 4; i++)
                #pragma unroll
                for (int j = 0; j < 4; j++) acc[i][j] = fmaf(aa[i], bb[j], acc[i][j]);
        }
        __syncthreads();
    }
    #pragma unroll
    for (int i = 0; i < 4; i++) {
        int r = bm + (ty << 2) + i;
        #pragma unroll
        for (int j = 0; j < 4; j++) {
            int c = bn + (tx << 2) + j;
            float v = acc[i][j] + bias[c];
            if (act) v = fmaxf(v, 0.f);
            C[(size_t)r*Nn + c] = v;
        }
    }
}

// ------------------------------ batchnorm (training stats over N rows) ------
__global__ void k_zstat() {
    int i = blockIdx.x * 256 + threadIdx.x;
    if (i < 2*EMB) { g_sum[i] = 0.f; g_sq[i] = 0.f; }
}

__global__ void k_bnstats(const float* __restrict__ X, int C) {
    int r0 = blockIdx.x * 128;
    for (int c = threadIdx.x; c < C; c += 256) {
        float s = 0.f, q = 0.f;
        for (int r = 0; r < 128; r++) {
            float v = X[(size_t)(r0 + r)*C + c];
            s += v; q += v * v;
        }
        atomicAdd(&g_sum[c], s);
        atomicAdd(&g_sq[c], q);
    }
}

__global__ void k_bnfin(const float* __restrict__ g, const float* __restrict__ b, int C) {
    int c = blockIdx.x * 256 + threadIdx.x;
    if (c >= C) return;
    float mu  = g_sum[c] * (1.f / NTOT);
    float var = g_sq[c] * (1.f / NTOT) - mu * mu;
    float sc  = g[c] * rsqrtf(var + 1e-5f);
    g_scale[c] = sc;
    g_shift[c] = b[c] - mu * sc;
}

__global__ void k_bnapply(const float* __restrict__ X, float* __restrict__ O,
                          int cmask, int act) {
    int idx = blockIdx.x * 256 + threadIdx.x;
    int c = idx & cmask;
    float v = X[idx] * g_scale[c] + g_shift[c];
    if (act) v = fmaxf(v, 0.f);
    O[idx] = v;
}

// vt[b] = sum_nodes hin + vn[b]
__global__ void k_vt() {
    int b = blockIdx.x, c = threadIdx.x;
    const float* base = g_hin + (size_t)b*NPG*EMB + c;
    float s = 0.f;
    for (int r = 0; r < NPG; r++) s += base[(size_t)r*EMB];
    g_vt[b*EMB + c] = s + g_vn[b*EMB + c];
}

__global__ void k_copy(float* __restrict__ out) {
    int idx = blockIdx.x * 256 + threadIdx.x;
    out[idx] = g_h[idx];
}

// ------------------------------ host orchestration --------------------------
extern "C" void kernel_launch(void* const* d_in, const int* in_sizes, int n_in,
                              void* d_out, int out_size) {
    // base index of atom_emb handles presence/absence of the scalar `order`
    const int ab = n_in - 19;
    const int*   atom_idx = (const int*)  d_in[0];
    const int*   lei      = (const int*)  d_in[1];
    const int*   eai      = (const int*)  d_in[2];
    const float* atom_emb = (const float*)d_in[ab + 0];
    const float* bemb_h   = (const float*)d_in[ab + 1];
    const float* elin_w   = (const float*)d_in[ab + 2];
    const float* elin_b   = (const float*)d_in[ab + 3];
    const float* bemb_l   = (const float*)d_in[ab + 4];
    const float* gin_eps  = (const float*)d_in[ab + 5];
    const float* mlp_w1   = (const float*)d_in[ab + 6];
    const float* mlp_b1   = (const float*)d_in[ab + 7];
    const float* bn_g     = (const float*)d_in[ab + 8];
    const float* bn_b     = (const float*)d_in[ab + 9];
    const float* mlp_w2   = (const float*)d_in[ab + 10];
    const float* mlp_b2   = (const float*)d_in[ab + 11];
    const float* obn_g    = (const float*)d_in[ab + 12];
    const float* obn_b    = (const float*)d_in[ab + 13];
    const float* vn_emb   = (const float*)d_in[ab + 14];
    const float* vn_w1    = (const float*)d_in[ab + 15];
    const float* vn_b1    = (const float*)d_in[ab + 16];
    const float* vn_w2    = (const float*)d_in[ab + 17];
    const float* vn_b2    = (const float*)d_in[ab + 18];
    float* out = (float*)d_out;

    float *p_x1, *p_x2, *p_z, *p_t, *p_h2, *p_h, *p_vt, *p_vh, *p_vn;
    cudaGetSymbolAddress((void**)&p_x1, g_x1);
    cudaGetSymbolAddress((void**)&p_x2, g_x2);
    cudaGetSymbolAddress((void**)&p_z,  g_z);
    cudaGetSymbolAddress((void**)&p_t,  g_t);
    cudaGetSymbolAddress((void**)&p_h2, g_h2);
    cudaGetSymbolAddress((void**)&p_h,  g_h);
    cudaGetSymbolAddress((void**)&p_vt, g_vt);
    cudaGetSymbolAddress((void**)&p_vh, g_vh);
    cudaGetSymbolAddress((void**)&p_vn, g_vn);

    const int NE = NTOT*EMB/256;       // 32768 blocks for node*emb elementwise

    // ---- setup: edge weights, adjacency, CSR, embedding gather ----
    k_zero<<<(int)(((size_t)BG*NPG*NPG + 255)/256), 256>>>();
    k_ewt<<<1, 512>>>(bemb_h, elin_w, elin_b);
    k_scatter<<<ETOT/256, 256>>>(lei, eai);
    k_adjfin<<<BG, 256>>>();
    k_scan<<<BG, 256>>>();
    k_csrfill<<<ETOT/256, 256>>>(lei, eai);
    k_gather<<<NE, 256>>>(atom_idx, atom_emb);

    // ---- propagation: y = (f + Af + A^2 f + A^3 f) / 4 ----
    dim3 pg(EMB/64, NPG/64, BG);
    k_propgemm<<<pg, 256>>>(p_x1, p_x2);
    k_propgemm<<<pg, 256>>>(p_x2, p_x1);
    k_propgemm<<<pg, 256>>>(p_x1, p_x2);
    k_scale<<<NE, 256>>>();

    k_initvn<<<BG*EMB/256, 256>>>(vn_emb);

    // ---- GIN + virtual-node stack ----
    for (int l = 0; l < NL; l++) {
        k_addvn<<<NE, 256>>>();
        k_agg<<<NTOT, 256>>>(bemb_l + (size_t)l*16*EMB, gin_eps + l);

        // z @ w1 + b1 -> t [N, 512]
        k_gemm<<<dim3(2*EMB/64, NTOT/64), 256>>>(
            p_z, mlp_w1 + (size_t)l*EMB*2*EMB, mlp_b1 + (size_t)l*2*EMB,
            p_t, NTOT, 2*EMB, EMB, 0);
        // BN1 + relu (in place)
        k_zstat<<<2, 256>>>();
        k_bnstats<<<NTOT/128, 256>>>(p_t, 2*EMB);
        k_bnfin<<<2, 256>>>(bn_g + (size_t)l*2*EMB, bn_b + (size_t)l*2*EMB, 2*EMB);
        k_bnapply<<<NTOT*2*EMB/256, 256>>>(p_t, p_t, 2*EMB - 1, 1);

        // t @ w2 + b2 -> h2 [N, 256]
        k_gemm<<<dim3(EMB/64, NTOT/64), 256>>>(
            p_t, mlp_w2 + (size_t)l*2*EMB*EMB, mlp_b2 + (size_t)l*EMB,
            p_h2, NTOT, EMB, 2*EMB, 0);
        // BN2 (+relu except last layer) -> new h
        k_zstat<<<2, 256>>>();
        k_bnstats<<<NTOT/128, 256>>>(p_h2, EMB);
        k_bnfin<<<1, 256>>>(obn_g + (size_t)l*EMB, obn_b + (size_t)l*EMB, EMB);
        k_bnapply<<<NE, 256>>>(p_h2, p_h, EMB - 1, (l < NL - 1) ? 1 : 0);

        // virtual node update (uses h_in saved by k_addvn, old vn)
        if (l < NL - 1) {
            k_vt<<<BG, 256>>>();
            k_gemm<<<dim3(2*EMB/64, BG/64), 256>>>(
                p_vt, vn_w1 + (size_t)l*EMB*2*EMB, vn_b1 + (size_t)l*2*EMB,
                p_vh, BG, 2*EMB, EMB, 1);
            k_gemm<<<dim3(EMB/64, BG/64), 256>>>(
                p_vh, vn_w2 + (size_t)l*2*EMB*EMB, vn_b2 + (size_t)l*EMB,
                p_vn, BG, EMB, 2*EMB, 1);
        }
    }

    k_copy<<<NE, 256>>>(out);
    (void)in_sizes; (void)out_size;
}

// round 3
// speedup vs baseline: 1.5673x; 1.5673x over previous
#include <cuda_runtime.h>
#include <cuda_bf16.h>
#include <math.h>

#define BG   128
#define NPG  256
#define EPG  2048
#define EMB  256
#define NL   5
#define NTOT (BG*NPG)     // 32768 nodes
#define ETOT (BG*EPG)     // 262144 edges

typedef unsigned long long ull;

// ------------------------------ scratch (device globals; no allocs) ---------
__device__ ull   g_pack[(size_t)BG*NPG*NPG];   // packed last-write-wins adjacency
__device__ float g_A   [(size_t)BG*NPG*NPG];   // normalized adjacency
__device__ float g_h  [NTOT*EMB];
__device__ float g_x1 [NTOT*EMB];
__device__ float g_x2 [NTOT*EMB];
__device__ float g_hin[NTOT*EMB];
__device__ float g_z  [NTOT*EMB];
__device__ float g_t  [NTOT*2*EMB];
__device__ float g_h2 [NTOT*EMB];
__device__ float g_vn [BG*EMB];
__device__ float g_vt [BG*EMB];
__device__ float g_vh [BG*2*EMB];
__device__ float g_ewt[16];
__device__ int   g_deg[NTOT];
__device__ int   g_ptr[NTOT];
__device__ int   g_cur[NTOT];
__device__ int   g_csrc[ETOT];
__device__ int   g_cea [ETOT];
__device__ float g_sum[2*EMB];
__device__ float g_sq [2*EMB];
__device__ float g_scale[2*EMB];
__device__ float g_shift[2*EMB];

// ------------------------------ setup kernels -------------------------------
__global__ void k_zero() {
    size_t i = (size_t)blockIdx.x * 256 + threadIdx.x;
    if (i < (size_t)BG*NPG*NPG) g_pack[i] = 0ull;
    if (i < NTOT) g_deg[i] = 0;
}

__global__ void k_ewt(const float* __restrict__ bh, const float* __restrict__ w,
                      const float* __restrict__ b) {
    int warp = threadIdx.x >> 5, lane = threadIdx.x & 31;
    if (warp < 16) {
        float v = bh[warp*64 + lane] * w[lane] + bh[warp*64 + 32 + lane] * w[32 + lane];
        #pragma unroll
        for (int o = 16; o; o >>= 1) v += __shfl_down_sync(0xffffffffu, v, o);
        if (lane == 0) g_ewt[warp] = 1.f / (1.f + expf(-(v + b[0])));
    }
}

__global__ void k_scatter(const int* __restrict__ lei, const int* __restrict__ eai) {
    int idx = blockIdx.x * 256 + threadIdx.x;
    if (idx >= ETOT) return;
    int b = idx / EPG, k = idx - b * EPG;
    int s = lei[(size_t)b*2*EPG + k];
    int d = lei[(size_t)b*2*EPG + EPG + k];
    int t = eai[idx];
    float w = g_ewt[t];
    ull key = ((ull)(k + 1) << 32) | (ull)__float_as_uint(w);
    atomicMax(&g_pack[(size_t)b*NPG*NPG + (size_t)s*NPG + d], key);
    atomicAdd(&g_deg[b*NPG + d], 1);
}

__global__ void k_adjfin() {
    int g = blockIdx.x, tid = threadIdx.x;
    __shared__ float cs[NPG], rs[NPG];
    const ull* P = g_pack + (size_t)g*NPG*NPG;
    float*     A = g_A    + (size_t)g*NPG*NPG;
    float c = 0.f;
    for (int i = 0; i < NPG; i++) {
        ull p = P[(size_t)i*NPG + tid];
        float v = p ? __uint_as_float((unsigned)(p & 0xffffffffu)) : 0.f;
        if (i == tid) v += 1.f;
        A[(size_t)i*NPG + tid] = v;
        c += v;
    }
    cs[tid] = rsqrtf(c);
    __syncthreads();
    float r = 0.f;
    for (int j = 0; j < NPG; j++) r += A[(size_t)tid*NPG + j];
    rs[tid] = rsqrtf(r);
    __syncthreads();
    for (int i = 0; i < NPG; i++)
        A[(size_t)i*NPG + tid] *= cs[i] * rs[tid];
}

__global__ void k_scan() {
    int g = blockIdx.x, tid = threadIdx.x;
    __shared__ int s[NPG];
    int d = g_deg[g*NPG + tid];
    s[tid] = d;
    __syncthreads();
    for (int off = 1; off < NPG; off <<= 1) {
        int v = (tid >= off) ? s[tid - off] : 0;
        __syncthreads();
        s[tid] += v;
        __syncthreads();
    }
    int excl = s[tid] - d;
    g_ptr[g*NPG + tid] = g*EPG + excl;
    g_cur[g*NPG + tid] = g*EPG + excl;
}

__global__ void k_csrfill(const int* __restrict__ lei, const int* __restrict__ eai) {
    int idx = blockIdx.x * 256 + threadIdx.x;
    if (idx >= ETOT) return;
    int b = idx / EPG, k = idx - b * EPG;
    int s = lei[(size_t)b*2*EPG + k];
    int d = lei[(size_t)b*2*EPG + EPG + k];
    int pos = atomicAdd(&g_cur[b*NPG + d], 1);
    g_csrc[pos] = b*NPG + s;
    g_cea [pos] = eai[idx];
}

__global__ void k_gather(const int* __restrict__ aidx, const float* __restrict__ aemb) {
    int idx = blockIdx.x * 256 + threadIdx.x;
    int n = idx >> 8, c = idx & 255;
    float v = aemb[aidx[n]*EMB + c];
    g_h[idx]  = v;
    g_x1[idx] = v;
}

// ------------------------------ bf16x3 tensor-core GEMM ---------------------
// fp32-accurate GEMM on tensor cores: x = hi + lo (bf16 split),
// A@B ~= Ah@Bh + Ah@Bl + Al@Bh   (element error ~2^-17)
// CTA tile 128x64x16, 8 warps (4x2), warp tile 32x32, mma.m16n8k16.bf16
#define BM 128
#define BN 64
#define BK 16
#define AST 12     // word stride of packed A rows (k2 = 0..7 used) -> conflict-free frags
#define BST 72     // word stride of packed B rows (72 % 32 == 8) -> conflict-free frags

// pack two floats (even-k, odd-k) into one bf16x2 word: upper = odd, lower = even
__device__ __forceinline__ unsigned pack2(float e, float o) {
    unsigned r;
    asm("cvt.rn.bf16x2.f32 %0, %1, %2;" : "=r"(r) : "f"(o), "f"(e));
    return r;
}

__device__ __forceinline__ void split2(float e, float o, unsigned &hi, unsigned &lo) {
    float he = __bfloat162float(__float2bfloat16(e));
    float ho = __bfloat162float(__float2bfloat16(o));
    hi = pack2(e, o);
    lo = pack2(e - he, o - ho);
}

#define MMA_BF16(c, a, b)                                                     \
    asm volatile(                                                             \
        "mma.sync.aligned.m16n8k16.row.col.f32.bf16.bf16.f32 "                \
        "{%0,%1,%2,%3}, {%4,%5,%6,%7}, {%8,%9}, {%0,%1,%2,%3};\n"             \
        : "+f"((c)[0]), "+f"((c)[1]), "+f"((c)[2]), "+f"((c)[3])              \
        : "r"((a)[0]), "r"((a)[1]), "r"((a)[2]), "r"((a)[3]),                 \
          "r"((b)[0]), "r"((b)[1]))

// mode: 0 = C=acc+bias, 1 = C=relu(acc+bias), 2 = C=acc, Y+=acc (no bias)
__global__ void __launch_bounds__(256)
k_mma(const float* __restrict__ A, const float* __restrict__ B,
      const float* __restrict__ bias, float* __restrict__ C, float* __restrict__ Y,
      int M, int N, int K, int mode,
      long strideA, long strideB, long strideC) {
    A += (size_t)blockIdx.z * strideA;
    B += (size_t)blockIdx.z * strideB;
    C += (size_t)blockIdx.z * strideC;
    if (Y) Y += (size_t)blockIdx.z * strideC;

    __shared__ unsigned Ah[BM][AST], Al[BM][AST];   // [m][k2] packed bf16x2
    __shared__ unsigned Bh[8][BST],  Bl[8][BST];    // [k2][n] packed bf16x2

    int tid  = threadIdx.x;
    int lane = tid & 31, warp = tid >> 5;
    int wm = warp >> 1, wn = warp & 1;          // 4x2 warp grid
    int bm = blockIdx.y * BM, bn = blockIdx.x * BN;

    // A copy indices: row tid/4 (+64), 4 consecutive k
    int a_r0 = tid >> 2;
    int a_c  = (tid & 3) << 2;       // k offset (4 floats)
    int a_k2 = (tid & 3) << 1;       // packed word offset
    // B copy indices: k-pair tid/32, 2 consecutive n
    int b_k2 = tid >> 5;             // 0..7
    int b_n  = (lane) << 1;          // 0..62

    int gid = lane >> 2, tig = lane & 3;

    float acc[2][4][4];
    #pragma unroll
    for (int i = 0; i < 2; i++)
        #pragma unroll
        for (int j = 0; j < 4; j++)
            #pragma unroll
            for (int r = 0; r < 4; r++) acc[i][j][r] = 0.f;

    for (int k0 = 0; k0 < K; k0 += BK) {
        // ---- load + split A tile 128x16 ----
        #pragma unroll
        for (int h = 0; h < 2; h++) {
            int r = a_r0 + h*64;
            float4 v = *reinterpret_cast<const float4*>(A + (size_t)(bm + r)*K + k0 + a_c);
            unsigned hi0, lo0, hi1, lo1;
            split2(v.x, v.y, hi0, lo0);
            split2(v.z, v.w, hi1, lo1);
            Ah[r][a_k2]   = hi0;  Al[r][a_k2]   = lo0;
            Ah[r][a_k2+1] = hi1;  Al[r][a_k2+1] = lo1;
        }
        // ---- load + split B tile 16x64 ----
        {
            const float* Bp = B + (size_t)(k0 + 2*b_k2)*N + bn + b_n;
            float2 ve = *reinterpret_cast<const float2*>(Bp);
            float2 vo = *reinterpret_cast<const float2*>(Bp + N);
            unsigned hi0, lo0, hi1, lo1;
            split2(ve.x, vo.x, hi0, lo0);
            split2(ve.y, vo.y, hi1, lo1);
            Bh[b_k2][b_n]   = hi0;  Bl[b_k2][b_n]   = lo0;
            Bh[b_k2][b_n+1] = hi1;  Bl[b_k2][b_n+1] = lo1;
        }
        __syncthreads();

        // ---- fragments ----
        unsigned ah[2][4], al[2][4], bh[4][2], bl[4][2];
        #pragma unroll
        for (int mf = 0; mf < 2; mf++) {
            int rm = wm*32 + mf*16 + gid;
            ah[mf][0] = Ah[rm    ][tig    ];
            ah[mf][1] = Ah[rm + 8][tig    ];
            ah[mf][2] = Ah[rm    ][tig + 4];
            ah[mf][3] = Ah[rm + 8][tig + 4];
            al[mf][0] = Al[rm    ][tig    ];
            al[mf][1] = Al[rm + 8][tig    ];
            al[mf][2] = Al[rm    ][tig + 4];
            al[mf][3] = Al[rm + 8][tig + 4];
        }
        #pragma unroll
        for (int nf = 0; nf < 4; nf++) {
            int cn = wn*32 + nf*8 + gid;
            bh[nf][0] = Bh[tig    ][cn];
            bh[nf][1] = Bh[tig + 4][cn];
            bl[nf][0] = Bl[tig    ][cn];
            bl[nf][1] = Bl[tig + 4][cn];
        }

        // ---- 3-product split MMA ----
        #pragma unroll
        for (int mf = 0; mf < 2; mf++)
            #pragma unroll
            for (int nf = 0; nf < 4; nf++) {
                float* c = acc[mf][nf];
                MMA_BF16(c, ah[mf], bl[nf]);
                MMA_BF16(c, al[mf], bh[nf]);
                MMA_BF16(c, ah[mf], bh[nf]);
            }
        __syncthreads();
    }

    // ---- epilogue ----
    #pragma unroll
    for (int mf = 0; mf < 2; mf++) {
        #pragma unroll
        for (int nf = 0; nf < 4; nf++) {
            int r0 = bm + wm*32 + mf*16 + gid;
            int c0 = bn + wn*32 + nf*8 + 2*tig;
            float* c = acc[mf][nf];
            #pragma unroll
            for (int half = 0; half < 2; half++) {
                int r = r0 + half*8;
                float v0 = c[half*2+0], v1 = c[half*2+1];
                if (mode != 2) {
                    v0 += bias[c0]; v1 += bias[c0+1];
                    if (mode == 1) { v0 = fmaxf(v0, 0.f); v1 = fmaxf(v1, 0.f); }
                    *reinterpret_cast<float2*>(C + (size_t)r*N + c0) = make_float2(v0, v1);
                } else {
                    *reinterpret_cast<float2*>(C + (size_t)r*N + c0) = make_float2(v0, v1);
                    float2* y = reinterpret_cast<float2*>(Y + (size_t)r*N + c0);
                    float2 yo = *y;
                    yo.x += v0; yo.y += v1;
                    *y = yo;
                }
            }
        }
    }
}

__global__ void k_scale() {
    int idx = blockIdx.x * 256 + threadIdx.x;
    g_h[idx] *= 0.25f;
}

// ------------------------------ GIN layer kernels ---------------------------
__global__ void k_initvn(const float* __restrict__ vemb) {
    int idx = blockIdx.x * 256 + threadIdx.x;
    g_vn[idx] = vemb[idx & 255];
}

__global__ void k_addvn() {
    int idx = blockIdx.x * 256 + threadIdx.x;
    int b = idx >> 16;
    int c = idx & 255;
    float v = g_h[idx] + g_vn[b*EMB + c];
    g_h[idx] = v;
    g_hin[idx] = v;
}

__global__ void k_agg(const float* __restrict__ eembL, const float* __restrict__ epsp) {
    int n = blockIdx.x, c = threadIdx.x;
    int start = g_ptr[n], deg = g_deg[n];
    float val = 0.f;
    for (int k = 0; k < deg; k++) {
        int s = g_csrc[start + k];
        int t = g_cea [start + k];
        float m = g_h[(size_t)s*EMB + c] + eembL[t*EMB + c];
        val += fmaxf(m, 0.f);
    }
    float eps = *epsp;
    g_z[(size_t)n*EMB + c] = (1.f + eps) * g_h[(size_t)n*EMB + c] + val;
}

// ------------------------------ batchnorm -----------------------------------
__global__ void k_zstat() {
    int i = blockIdx.x * 256 + threadIdx.x;
    if (i < 2*EMB) { g_sum[i] = 0.f; g_sq[i] = 0.f; }
}

__global__ void k_bnstats(const float* __restrict__ X, int C) {
    int r0 = blockIdx.x * 128;
    for (int c = threadIdx.x; c < C; c += 256) {
        float s = 0.f, q = 0.f;
        for (int r = 0; r < 128; r++) {
            float v = X[(size_t)(r0 + r)*C + c];
            s += v; q += v * v;
        }
        atomicAdd(&g_sum[c], s);
        atomicAdd(&g_sq[c], q);
    }
}

__global__ void k_bnfin(const float* __restrict__ g, const float* __restrict__ b, int C) {
    int c = blockIdx.x * 256 + threadIdx.x;
    if (c >= C) return;
    float mu  = g_sum[c] * (1.f / NTOT);
    float var = g_sq[c] * (1.f / NTOT) - mu * mu;
    float sc  = g[c] * rsqrtf(var + 1e-5f);
    g_scale[c] = sc;
    g_shift[c] = b[c] - mu * sc;
}

__global__ void k_bnapply(const float* __restrict__ X, float* __restrict__ O,
                          int cmask, int act) {
    int idx = blockIdx.x * 256 + threadIdx.x;
    int c = idx & cmask;
    float v = X[idx] * g_scale[c] + g_shift[c];
    if (act) v = fmaxf(v, 0.f);
    O[idx] = v;
}

__global__ void k_vt() {
    int b = blockIdx.x, c = threadIdx.x;
    const float* base = g_hin + (size_t)b*NPG*EMB + c;
    float s = 0.f;
    for (int r = 0; r < NPG; r++) s += base[(size_t)r*EMB];
    g_vt[b*EMB + c] = s + g_vn[b*EMB + c];
}

__global__ void k_copy(float* __restrict__ out) {
    int idx = blockIdx.x * 256 + threadIdx.x;
    out[idx] = g_h[idx];
}

// ------------------------------ host orchestration --------------------------
extern "C" void kernel_launch(void* const* d_in, const int* in_sizes, int n_in,
                              void* d_out, int out_size) {
    const int ab = n_in - 19;
    const int*   atom_idx = (const int*)  d_in[0];
    const int*   lei      = (const int*)  d_in[1];
    const int*   eai      = (const int*)  d_in[2];
    const float* atom_emb = (const float*)d_in[ab + 0];
    const float* bemb_h   = (const float*)d_in[ab + 1];
    const float* elin_w   = (const float*)d_in[ab + 2];
    const float* elin_b   = (const float*)d_in[ab + 3];
    const float* bemb_l   = (const float*)d_in[ab + 4];
    const float* gin_eps  = (const float*)d_in[ab + 5];
    const float* mlp_w1   = (const float*)d_in[ab + 6];
    const float* mlp_b1   = (const float*)d_in[ab + 7];
    const float* bn_g     = (const float*)d_in[ab + 8];
    const float* bn_b     = (const float*)d_in[ab + 9];
    const float* mlp_w2   = (const float*)d_in[ab + 10];
    const float* mlp_b2   = (const float*)d_in[ab + 11];
    const float* obn_g    = (const float*)d_in[ab + 12];
    const float* obn_b    = (const float*)d_in[ab + 13];
    const float* vn_emb   = (const float*)d_in[ab + 14];
    const float* vn_w1    = (const float*)d_in[ab + 15];
    const float* vn_b1    = (const float*)d_in[ab + 16];
    const float* vn_w2    = (const float*)d_in[ab + 17];
    const float* vn_b2    = (const float*)d_in[ab + 18];
    float* out = (float*)d_out;

    float *p_x1, *p_x2, *p_z, *p_t, *p_h2, *p_h, *p_vt, *p_vh, *p_vn, *p_A;
    cudaGetSymbolAddress((void**)&p_x1, g_x1);
    cudaGetSymbolAddress((void**)&p_x2, g_x2);
    cudaGetSymbolAddress((void**)&p_z,  g_z);
    cudaGetSymbolAddress((void**)&p_t,  g_t);
    cudaGetSymbolAddress((void**)&p_h2, g_h2);
    cudaGetSymbolAddress((void**)&p_h,  g_h);
    cudaGetSymbolAddress((void**)&p_vt, g_vt);
    cudaGetSymbolAddress((void**)&p_vh, g_vh);
    cudaGetSymbolAddress((void**)&p_vn, g_vn);
    cudaGetSymbolAddress((void**)&p_A,  g_A);

    const int NE = NTOT*EMB/256;

    // ---- setup ----
    k_zero<<<(int)(((size_t)BG*NPG*NPG + 255)/256), 256>>>();
    k_ewt<<<1, 512>>>(bemb_h, elin_w, elin_b);
    k_scatter<<<ETOT/256, 256>>>(lei, eai);
    k_adjfin<<<BG, 256>>>();
    k_scan<<<BG, 256>>>();
    k_csrfill<<<ETOT/256, 256>>>(lei, eai);
    k_gather<<<NE, 256>>>(atom_idx, atom_emb);

    // ---- propagation: y = (f + Af + A^2 f + A^3 f) / 4 ----
    dim3 pgrid(NPG/BN, NPG/BM, BG);   // (4, 2, 128)
    long sA = (long)NPG*NPG, sX = (long)NPG*EMB;
    k_mma<<<pgrid, 256>>>(p_A, p_x1, nullptr, p_x2, p_h, NPG, EMB, NPG, 2, sA, sX, sX);
    k_mma<<<pgrid, 256>>>(p_A, p_x2, nullptr, p_x1, p_h, NPG, EMB, NPG, 2, sA, sX, sX);
    k_mma<<<pgrid, 256>>>(p_A, p_x1, nullptr, p_x2, p_h, NPG, EMB, NPG, 2, sA, sX, sX);
    k_scale<<<NE, 256>>>();

    k_initvn<<<BG*EMB/256, 256>>>(vn_emb);

    // ---- GIN + virtual-node stack ----
    for (int l = 0; l < NL; l++) {
        k_addvn<<<NE, 256>>>();
        k_agg<<<NTOT, 256>>>(bemb_l + (size_t)l*16*EMB, gin_eps + l);

        // z @ w1 + b1 -> t [N, 512]
        k_mma<<<dim3(2*EMB/BN, NTOT/BM, 1), 256>>>(
            p_z, mlp_w1 + (size_t)l*EMB*2*EMB, mlp_b1 + (size_t)l*2*EMB,
            p_t, nullptr, NTOT, 2*EMB, EMB, 0, 0, 0, 0);
        // BN1 + relu (in place)
        k_zstat<<<2, 256>>>();
        k_bnstats<<<NTOT/128, 256>>>(p_t, 2*EMB);
        k_bnfin<<<2, 256>>>(bn_g + (size_t)l*2*EMB, bn_b + (size_t)l*2*EMB, 2*EMB);
        k_bnapply<<<NTOT*2*EMB/256, 256>>>(p_t, p_t, 2*EMB - 1, 1);

        // t @ w2 + b2 -> h2 [N, 256]
        k_mma<<<dim3(EMB/BN, NTOT/BM, 1), 256>>>(
            p_t, mlp_w2 + (size_t)l*2*EMB*EMB, mlp_b2 + (size_t)l*EMB,
            p_h2, nullptr, NTOT, EMB, 2*EMB, 0, 0, 0, 0);
        // BN2 (+relu except last layer) -> new h
        k_zstat<<<2, 256>>>();
        k_bnstats<<<NTOT/128, 256>>>(p_h2, EMB);
        k_bnfin<<<1, 256>>>(obn_g + (size_t)l*EMB, obn_b + (size_t)l*EMB, EMB);
        k_bnapply<<<NE, 256>>>(p_h2, p_h, EMB - 1, (l < NL - 1) ? 1 : 0);

        // virtual node update
        if (l < NL - 1) {
            k_vt<<<BG, 256>>>();
            k_mma<<<dim3(2*EMB/BN, BG/BM, 1), 256>>>(
                p_vt, vn_w1 + (size_t)l*EMB*2*EMB, vn_b1 + (size_t)l*2*EMB,
                p_vh, nullptr, BG, 2*EMB, EMB, 1, 0, 0, 0);
            k_mma<<<dim3(EMB/BN, BG/BM, 1), 256>>>(
                p_vh, vn_w2 + (size_t)l*2*EMB*EMB, vn_b2 + (size_t)l*EMB,
                p_vn, nullptr, BG, EMB, 2*EMB, 1, 0, 0, 0);
        }
    }

    k_copy<<<NE, 256>>>(out);
    (void)in_sizes; (void)out_size;
}